// round 2
// baseline (speedup 1.0000x reference)
#include <cuda_runtime.h>
#include <math.h>

// Problem constants
#define Bq 4
#define Tt 256
#define Dd 256
#define D2 512
#define BT 1024
#define SCALEF 0.0625f

// GEMM tile
#define BM 64
#define BN 64
#define BK 16

// ---------------- scratch (static device globals; no allocation) -------------
__device__ float g_xnorm[BT * Dd];
__device__ float g_xleft[BT * D2];
__device__ float g_xright[BT * D2];
__device__ float g_xtrans[BT * D2];
__device__ float g_o[BT * D2];
__device__ float g_q[BT * D2];
__device__ float g_k[BT * D2];
__device__ float g_v[BT * D2];
__device__ float g_hseq[BT * D2];
__device__ float g_h[BT * D2];
__device__ float g_convwt[4 * D2 * D2];
__device__ float g_A[Bq * Tt * Tt];
__device__ float g_ib[BT];
__device__ float g_fb[BT];
__device__ float g_alpha[BT];
__device__ float g_beta[BT];
__device__ float g_rowsum[BT];
__device__ float g_gnmu[16];
__device__ float g_gnrs[16];

__device__ __forceinline__ float sigm(float x) { return 1.f / (1.f + __expf(-x)); }

// ---------------- LayerNorm ----------------
__global__ void k_layernorm(const float* __restrict__ x, const float* __restrict__ g,
                            const float* __restrict__ b) {
    int row = blockIdx.x, tid = threadIdx.x;  // 256 threads, one per element
    float v = x[row * Dd + tid];
    float s = v, s2 = v * v;
#pragma unroll
    for (int o = 16; o; o >>= 1) {
        s += __shfl_xor_sync(0xffffffffu, s, o);
        s2 += __shfl_xor_sync(0xffffffffu, s2, o);
    }
    __shared__ float sh[8], sh2[8];
    int w = tid >> 5, l = tid & 31;
    if (l == 0) { sh[w] = s; sh2[w] = s2; }
    __syncthreads();
    if (tid == 0) {
        float a = 0, a2 = 0;
#pragma unroll
        for (int i = 0; i < 8; i++) { a += sh[i]; a2 += sh2[i]; }
        sh[0] = a; sh2[0] = a2;
    }
    __syncthreads();
    float mu = sh[0] * (1.f / Dd);
    float var = sh2[0] * (1.f / Dd) - mu * mu;
    float r = rsqrtf(var + 1e-5f);
    g_xnorm[row * Dd + tid] = (v - mu) * r * g[tid] + b[tid];
}

// ---------------- conv_w transpose: (O,I,4) -> (4,O,I) ----------------
__global__ void k_convwt(const float* __restrict__ cw) {
    int idx = blockIdx.x * 256 + threadIdx.x;  // o*512 + i, 262144 total
    float4 w = *(const float4*)(cw + (size_t)idx * 4);
    g_convwt[0 * 262144 + idx] = w.x;
    g_convwt[1 * 262144 + idx] = w.y;
    g_convwt[2 * 262144 + idx] = w.z;
    g_convwt[3 * 262144 + idx] = w.w;
}

// ---------------- shared-tile MMA core ----------------
__device__ __forceinline__ void mma_tile(const float (*As)[BM], const float (*Bs)[BN],
                                         int ty, int tx, float acc[4][4]) {
#pragma unroll
    for (int kk = 0; kk < BK; kk++) {
        float4 av = *(const float4*)&As[kk][ty * 4];
        float4 bv = *(const float4*)&Bs[kk][tx * 4];
        float ar[4] = {av.x, av.y, av.z, av.w};
        float br[4] = {bv.x, bv.y, bv.z, bv.w};
#pragma unroll
        for (int i = 0; i < 4; i++)
#pragma unroll
            for (int j = 0; j < 4; j++) acc[i][j] += ar[i] * br[j];
    }
}

// ---------------- generic TN GEMM: C = A(MxK) @ W(NxK)^T, epilogues ----------
// epi 0: C = acc + bias[n]
// epi 1: C = sigmoid(acc + bias[n])
// epi 2: skip/groupnorm epilogue (bias=gn_g, extra=gn_b) -> g_h
// epi 3: final: C = acc + bias[n] + extra[m*N+n] (residual)
__global__ __launch_bounds__(256) void k_gemm(const float* __restrict__ A,
                                              const float* __restrict__ W,
                                              const float* __restrict__ bias,
                                              const float* __restrict__ extra,
                                              float* __restrict__ C, int N, int K, int epi) {
    __shared__ __align__(16) float As[BK][BM];
    __shared__ __align__(16) float Bs[BK][BN];
    int tid = threadIdx.x;
    int m0 = blockIdx.y * BM, n0 = blockIdx.x * BN;
    int lr = tid >> 2, lk = (tid & 3) * 4;
    int ty = tid >> 4, tx = tid & 15;
    const float* Ap = A + (size_t)(m0 + lr) * K + lk;
    const float* Wp = W + (size_t)(n0 + lr) * K + lk;
    float acc[4][4] = {};
    for (int k0 = 0; k0 < K; k0 += BK) {
        float4 a = *(const float4*)(Ap + k0);
        float4 w = *(const float4*)(Wp + k0);
        As[lk + 0][lr] = a.x; As[lk + 1][lr] = a.y; As[lk + 2][lr] = a.z; As[lk + 3][lr] = a.w;
        Bs[lk + 0][lr] = w.x; Bs[lk + 1][lr] = w.y; Bs[lk + 2][lr] = w.z; Bs[lk + 3][lr] = w.w;
        __syncthreads();
        mma_tile(As, Bs, ty, tx, acc);
        __syncthreads();
    }
#pragma unroll
    for (int i = 0; i < 4; i++) {
        int m = m0 + ty * 4 + i;
#pragma unroll
        for (int j = 0; j < 4; j++) {
            int n = n0 + tx * 4 + j;
            float v = acc[i][j];
            if (epi == 0) {
                C[(size_t)m * N + n] = v + bias[n];
            } else if (epi == 1) {
                C[(size_t)m * N + n] = sigm(v + bias[n]);
            } else if (epi == 2) {
                int b = m >> 8, hh = n >> 7;
                float mu = g_gnmu[b * 4 + hh], rs = g_gnrs[b * 4 + hh];
                float zn = (g_hseq[(size_t)m * D2 + n] - mu) * rs;
                float hg = zn * bias[n] + extra[n] + v;
                float xr = g_xright[(size_t)m * D2 + n];
                C[(size_t)m * N + n] = hg * xr * sigm(xr);
            } else {
                C[(size_t)m * N + n] = v + bias[n] + extra[(size_t)m * N + n];
            }
        }
    }
}

// ---------------- causal conv1d (k=4, left pad 3) as GEMM, swish epilogue ----
__global__ __launch_bounds__(256) void k_conv(const float* __restrict__ cb) {
    __shared__ __align__(16) float As[BK][BM];
    __shared__ __align__(16) float Bs[BK][BN];
    int tid = threadIdx.x;
    int m0 = blockIdx.y * BM, n0 = blockIdx.x * BN;
    int lr = tid >> 2, lk = (tid & 3) * 4;
    int ty = tid >> 4, tx = tid & 15;
    int row = m0 + lr, b = row >> 8, t = row & 255;
    float acc[4][4] = {};
    for (int k0 = 0; k0 < 2048; k0 += BK) {
        int tau = k0 >> 9;
        int i = (k0 & 511) + lk;
        int tp = t - 3 + tau;
        float4 a = make_float4(0.f, 0.f, 0.f, 0.f);
        if (tp >= 0) a = *(const float4*)(g_xleft + (size_t)(b * Tt + tp) * D2 + i);
        float4 w = *(const float4*)(g_convwt + (size_t)tau * D2 * D2 + (size_t)(n0 + lr) * D2 + i);
        As[lk + 0][lr] = a.x; As[lk + 1][lr] = a.y; As[lk + 2][lr] = a.z; As[lk + 3][lr] = a.w;
        Bs[lk + 0][lr] = w.x; Bs[lk + 1][lr] = w.y; Bs[lk + 2][lr] = w.z; Bs[lk + 3][lr] = w.w;
        __syncthreads();
        mma_tile(As, Bs, ty, tx, acc);
        __syncthreads();
    }
#pragma unroll
    for (int i = 0; i < 4; i++) {
        int m = m0 + ty * 4 + i;
#pragma unroll
        for (int j = 0; j < 4; j++) {
            int n = n0 + tx * 4 + j;
            float z = acc[i][j] + cb[n];
            g_xtrans[(size_t)m * D2 + n] = z * sigm(z);
        }
    }
}

// ---------------- block-diagonal q/k/v projections ----------------
// grid.z = which*4 + head; which: 0=q (from x_trans), 1=k (x_trans, *SCALE), 2=v (x_left)
__global__ __launch_bounds__(256) void k_qkv(const float* __restrict__ Wq,
                                             const float* __restrict__ Wk,
                                             const float* __restrict__ Wv) {
    __shared__ __align__(16) float As[BK][BM];
    __shared__ __align__(16) float Bs[BK][BN];
    int tid = threadIdx.x;
    int z = blockIdx.z, which = z >> 2, h = z & 3;
    const float* src = (which == 2) ? g_xleft : g_xtrans;
    const float* W = (which == 0) ? Wq : ((which == 1) ? Wk : Wv);
    float* dst = (which == 0) ? g_q : ((which == 1) ? g_k : g_v);
    float sc = (which == 1) ? SCALEF : 1.f;
    int m0 = blockIdx.y * BM, n0 = blockIdx.x * BN;
    int lr = tid >> 2, lk = (tid & 3) * 4;
    int ty = tid >> 4, tx = tid & 15;
    const float* Ap = src + (size_t)(m0 + lr) * D2 + h * 128 + lk;
    const float* Wp = W + (size_t)h * 16384 + (size_t)(n0 + lr) * 128 + lk;
    float acc[4][4] = {};
    for (int k0 = 0; k0 < 128; k0 += BK) {
        float4 a = *(const float4*)(Ap + k0);
        float4 w = *(const float4*)(Wp + k0);
        As[lk + 0][lr] = a.x; As[lk + 1][lr] = a.y; As[lk + 2][lr] = a.z; As[lk + 3][lr] = a.w;
        Bs[lk + 0][lr] = w.x; Bs[lk + 1][lr] = w.y; Bs[lk + 2][lr] = w.z; Bs[lk + 3][lr] = w.w;
        __syncthreads();
        mma_tile(As, Bs, ty, tx, acc);
        __syncthreads();
    }
#pragma unroll
    for (int i = 0; i < 4; i++)
#pragma unroll
        for (int j = 0; j < 4; j++)
            dst[(size_t)(m0 + ty * 4 + i) * D2 + h * 128 + n0 + tx * 4 + j] = sc * acc[i][j];
}

// ---------------- i_bar / f_bar GEMV + zero rowsum ----------------
__global__ void k_ibfb(const float* __restrict__ Wi, const float* __restrict__ Wf,
                       const float* __restrict__ bi, const float* __restrict__ bf) {
    int row = blockIdx.x * 8 + (threadIdx.x >> 5);
    int l = threadIdx.x & 31;
    const float* xr = g_xleft + (size_t)row * D2;
    float si = 0, sf = 0;
#pragma unroll 4
    for (int j = l; j < D2; j += 32) {
        float v = xr[j];
        si += v * Wi[j];
        sf += v * Wf[j];
    }
#pragma unroll
    for (int o = 16; o; o >>= 1) {
        si += __shfl_xor_sync(0xffffffffu, si, o);
        sf += __shfl_xor_sync(0xffffffffu, sf, o);
    }
    if (l == 0) {
        g_ib[row] = si + bi[0];
        g_fb[row] = sf + bf[0];
        g_rowsum[row] = 0.f;
    }
}

// ---------------- scalar gate scan: m_t, F_t -> alpha, beta ----------------
__global__ void k_scan() {
    int b = threadIdx.x;
    if (b < Bq) {
        float m = 0.f, F = 0.f;
        for (int t = 0; t < Tt; t++) {
            float ib = g_ib[b * Tt + t], fb = g_fb[b * Tt + t];
            float mn = fmaxf(fb + m, ib);
            F += fb;
            g_alpha[b * Tt + t] = ib - F;   // ib_s - F_s
            g_beta[b * Tt + t] = F - mn;    // F_t - m_t
            m = mn;
        }
    }
}

// ---------------- attention scores: A[t][s] = exp(a_s+b_t) * (q_t . k_s) ----
__global__ __launch_bounds__(256) void k_attn1() {
    __shared__ __align__(16) float As[BK][BM];
    __shared__ __align__(16) float Bs[BK][BN];
    int tid = threadIdx.x;
    int z = blockIdx.z;
    int m0 = blockIdx.y * BM, n0 = blockIdx.x * BN;
    int lr = tid >> 2, lk = (tid & 3) * 4;
    int ty = tid >> 4, tx = tid & 15;
    const float* Ap = g_q + (size_t)(z * Tt + m0 + lr) * D2 + lk;
    const float* Wp = g_k + (size_t)(z * Tt + n0 + lr) * D2 + lk;
    float acc[4][4] = {};
    for (int k0 = 0; k0 < D2; k0 += BK) {
        float4 a = *(const float4*)(Ap + k0);
        float4 w = *(const float4*)(Wp + k0);
        As[lk + 0][lr] = a.x; As[lk + 1][lr] = a.y; As[lk + 2][lr] = a.z; As[lk + 3][lr] = a.w;
        Bs[lk + 0][lr] = w.x; Bs[lk + 1][lr] = w.y; Bs[lk + 2][lr] = w.z; Bs[lk + 3][lr] = w.w;
        __syncthreads();
        mma_tile(As, Bs, ty, tx, acc);
        __syncthreads();
    }
    float al[4], be[4];
#pragma unroll
    for (int j = 0; j < 4; j++) al[j] = g_alpha[z * Tt + n0 + tx * 4 + j];
#pragma unroll
    for (int i = 0; i < 4; i++) be[i] = g_beta[z * Tt + m0 + ty * 4 + i];
#pragma unroll
    for (int i = 0; i < 4; i++) {
        int t = m0 + ty * 4 + i;
        float p = 0.f;
#pragma unroll
        for (int j = 0; j < 4; j++) {
            int s = n0 + tx * 4 + j;
            float v = (s <= t) ? __expf(al[j] + be[i]) * acc[i][j] : 0.f;
            g_A[(size_t)z * Tt * Tt + (size_t)t * Tt + s] = v;
            p += v;
        }
        // butterfly reduce across the 16 tx lanes of this half-warp (row t)
#pragma unroll
        for (int off = 1; off < 16; off <<= 1) p += __shfl_xor_sync(0xffffffffu, p, off);
        if (tx == 0) atomicAdd(&g_rowsum[z * Tt + t], p);
    }
}

// ---------------- h = (A @ V) / denom * o (NN GEMM) ----------------
__global__ __launch_bounds__(256) void k_attn2() {
    __shared__ __align__(16) float As[BK][BM];
    __shared__ __align__(16) float Bs[BK][BN];
    int tid = threadIdx.x;
    int z = blockIdx.z;
    int m0 = blockIdx.y * BM, n0 = blockIdx.x * BN;
    int lr = tid >> 2, lk = (tid & 3) * 4;
    int ty = tid >> 4, tx = tid & 15;
    int brow = tid >> 4, bcol = (tid & 15) * 4;
    const float* Ap = g_A + (size_t)z * Tt * Tt + (size_t)(m0 + lr) * Tt + lk;
    const float* Vb = g_v + (size_t)z * Tt * D2;
    float acc[4][4] = {};
    for (int k0 = 0; k0 < Tt; k0 += BK) {
        float4 a = *(const float4*)(Ap + k0);
        float4 w = *(const float4*)(Vb + (size_t)(k0 + brow) * D2 + n0 + bcol);
        As[lk + 0][lr] = a.x; As[lk + 1][lr] = a.y; As[lk + 2][lr] = a.z; As[lk + 3][lr] = a.w;
        *(float4*)&Bs[brow][bcol] = w;
        __syncthreads();
        mma_tile(As, Bs, ty, tx, acc);
        __syncthreads();
    }
#pragma unroll
    for (int i = 0; i < 4; i++) {
        int m = m0 + ty * 4 + i;
        int r = z * Tt + m;
        float rs = g_rowsum[r];
        float dn = fmaxf(fabsf(rs), 1.f) + 1e-8f;
        float inv = 1.f / dn;
#pragma unroll
        for (int j = 0; j < 4; j++) {
            int n = n0 + tx * 4 + j;
            g_hseq[(size_t)r * D2 + n] = acc[i][j] * inv * g_o[(size_t)r * D2 + n];
        }
    }
}

// ---------------- GroupNorm stats over (T, DH) per (b, h) ----------------
__global__ void k_gnstats() {
    int bh = blockIdx.x;
    int b = bh >> 2, h = bh & 3;
    int tid = threadIdx.x;
    float s = 0, s2 = 0;
    const float* base = g_hseq + (size_t)(b * Tt) * D2 + h * 128;
    for (int i = tid; i < Tt * 128; i += 256) {
        int t = i >> 7, d = i & 127;
        float v = base[(size_t)t * D2 + d];
        s += v; s2 += v * v;
    }
#pragma unroll
    for (int o = 16; o; o >>= 1) {
        s += __shfl_xor_sync(0xffffffffu, s, o);
        s2 += __shfl_xor_sync(0xffffffffu, s2, o);
    }
    __shared__ float sh[8], sh2[8];
    int w = tid >> 5, l = tid & 31;
    if (l == 0) { sh[w] = s; sh2[w] = s2; }
    __syncthreads();
    if (tid == 0) {
        float a = 0, a2 = 0;
#pragma unroll
        for (int i = 0; i < 8; i++) { a += sh[i]; a2 += sh2[i]; }
        float mu = a * (1.f / (Tt * 128));
        float var = a2 * (1.f / (Tt * 128)) - mu * mu;
        g_gnmu[bh] = mu;
        g_gnrs[bh] = rsqrtf(var + 1e-5f);
    }
}

// ---------------- launch ----------------
extern "C" void kernel_launch(void* const* d_in, const int* in_sizes, int n_in,
                              void* d_out, int out_size) {
    const float* x       = (const float*)d_in[0];
    const float* ln_g    = (const float*)d_in[1];
    const float* ln_b    = (const float*)d_in[2];
    const float* W_left  = (const float*)d_in[3];
    const float* b_left  = (const float*)d_in[4];
    const float* W_right = (const float*)d_in[5];
    const float* b_right = (const float*)d_in[6];
    const float* Wi      = (const float*)d_in[7];
    const float* bi      = (const float*)d_in[8];
    const float* Wf      = (const float*)d_in[9];
    const float* bf      = (const float*)d_in[10];
    const float* Wo      = (const float*)d_in[11];
    const float* bo      = (const float*)d_in[12];
    const float* Wq      = (const float*)d_in[13];
    const float* Wk      = (const float*)d_in[14];
    const float* Wv      = (const float*)d_in[15];
    const float* conv_w  = (const float*)d_in[16];
    const float* conv_b  = (const float*)d_in[17];
    const float* skip_W  = (const float*)d_in[18];
    const float* gn_g    = (const float*)d_in[19];
    const float* gn_b    = (const float*)d_in[20];
    const float* W_last  = (const float*)d_in[21];
    const float* b_last  = (const float*)d_in[22];
    float* out = (float*)d_out;

    float *p_xnorm, *p_xleft, *p_xright, *p_xtrans, *p_o, *p_h;
    cudaGetSymbolAddress((void**)&p_xnorm, g_xnorm);
    cudaGetSymbolAddress((void**)&p_xleft, g_xleft);
    cudaGetSymbolAddress((void**)&p_xright, g_xright);
    cudaGetSymbolAddress((void**)&p_xtrans, g_xtrans);
    cudaGetSymbolAddress((void**)&p_o, g_o);
    cudaGetSymbolAddress((void**)&p_h, g_h);

    k_layernorm<<<BT, 256>>>(x, ln_g, ln_b);
    k_convwt<<<1024, 256>>>(conv_w);
    k_gemm<<<dim3(8, 16), 256>>>(p_xnorm, W_left, b_left, nullptr, p_xleft, 512, 256, 0);
    k_gemm<<<dim3(8, 16), 256>>>(p_xnorm, W_right, b_right, nullptr, p_xright, 512, 256, 0);
    k_conv<<<dim3(8, 16), 256>>>(conv_b);
    k_gemm<<<dim3(8, 16), 256>>>(p_xleft, Wo, bo, nullptr, p_o, 512, 512, 1);
    k_ibfb<<<128, 256>>>(Wi, Wf, bi, bf);
    k_scan<<<1, 32>>>();
    k_qkv<<<dim3(2, 16, 12), 256>>>(Wq, Wk, Wv);
    k_attn1<<<dim3(4, 4, 4), 256>>>();
    k_attn2<<<dim3(8, 4, 4), 256>>>();
    k_gnstats<<<16, 256>>>();
    k_gemm<<<dim3(8, 16), 256>>>(p_xtrans, skip_W, gn_g, gn_b, p_h, 512, 512, 2);
    k_gemm<<<dim3(4, 16), 256>>>(p_h, W_last, b_last, x, out, 256, 512, 3);
}

// round 3
// speedup vs baseline: 1.4059x; 1.4059x over previous
#include <cuda_runtime.h>
#include <math.h>

typedef unsigned long long ull;

// Problem constants
#define Bq 4
#define Tt 256
#define Dd 256
#define D2 512
#define BT 1024
#define SCALEF 0.0625f

// GEMM tile
#define BM 64
#define BN 64
#define BK 16

// ---------------- scratch (static device globals; no allocation) -------------
__device__ float g_xnorm[BT * Dd];
__device__ float g_xleft[BT * D2];
__device__ float g_xright[BT * D2];
__device__ float g_xtrans[BT * D2];
__device__ float g_o[BT * D2];
__device__ float g_q[BT * D2];
__device__ float g_k[BT * D2];
__device__ float g_v[BT * D2];
__device__ float g_hseq[BT * D2];
__device__ float g_h[BT * D2];
__device__ float g_convwt[4 * D2 * D2];
__device__ float g_A[Bq * Tt * Tt];
__device__ float g_ib[BT];
__device__ float g_fb[BT];
__device__ float g_alpha[BT];
__device__ float g_beta[BT];
__device__ float g_rowsum[BT];
__device__ float g_gnmu[16];
__device__ float g_gnrs[16];

__device__ __forceinline__ float sigm(float x) { return 1.f / (1.f + __expf(-x)); }

// ---------------- packed f32x2 helpers ----------------
__device__ __forceinline__ ull packf2(float lo, float hi) {
    ull r; asm("mov.b64 %0, {%1, %2};" : "=l"(r) : "f"(lo), "f"(hi)); return r;
}
__device__ __forceinline__ void fma2(ull& d, ull a, ull b) {
    asm("fma.rn.f32x2 %0, %1, %2, %0;" : "+l"(d) : "l"(a), "l"(b));
}
__device__ __forceinline__ float2 unpackf2(ull v) {
    float2 f; asm("mov.b64 {%0, %1}, %2;" : "=f"(f.x), "=f"(f.y) : "l"(v)); return f;
}

// ---------------- packed shared-tile MMA core ----------------
__device__ __forceinline__ void mma_tile2(const float (*As)[BM + 4], const float (*Bs)[BN + 4],
                                          int ty, int tx, ull acc[4][2]) {
#pragma unroll
    for (int kk = 0; kk < BK; kk++) {
        float4 av = *(const float4*)&As[kk][ty * 4];
        float4 bv = *(const float4*)&Bs[kk][tx * 4];
        ull bp0 = packf2(bv.x, bv.y), bp1 = packf2(bv.z, bv.w);
        float ar[4] = {av.x, av.y, av.z, av.w};
#pragma unroll
        for (int i = 0; i < 4; i++) {
            ull ap = packf2(ar[i], ar[i]);
            fma2(acc[i][0], ap, bp0);
            fma2(acc[i][1], ap, bp1);
        }
    }
}

#define STS_TILE(BUF, AV, WV)                                                        \
    do {                                                                             \
        As[BUF][lk + 0][lr] = (AV).x; As[BUF][lk + 1][lr] = (AV).y;                  \
        As[BUF][lk + 2][lr] = (AV).z; As[BUF][lk + 3][lr] = (AV).w;                  \
        Bs[BUF][lk + 0][lr] = (WV).x; Bs[BUF][lk + 1][lr] = (WV).y;                  \
        Bs[BUF][lk + 2][lr] = (WV).z; Bs[BUF][lk + 3][lr] = (WV).w;                  \
    } while (0)

// ---------------- LayerNorm ----------------
__global__ void k_layernorm(const float* __restrict__ x, const float* __restrict__ g,
                            const float* __restrict__ b) {
    int row = blockIdx.x, tid = threadIdx.x;
    float v = x[row * Dd + tid];
    float s = v, s2 = v * v;
#pragma unroll
    for (int o = 16; o; o >>= 1) {
        s += __shfl_xor_sync(0xffffffffu, s, o);
        s2 += __shfl_xor_sync(0xffffffffu, s2, o);
    }
    __shared__ float sh[8], sh2[8];
    int w = tid >> 5, l = tid & 31;
    if (l == 0) { sh[w] = s; sh2[w] = s2; }
    __syncthreads();
    if (tid == 0) {
        float a = 0, a2 = 0;
#pragma unroll
        for (int i = 0; i < 8; i++) { a += sh[i]; a2 += sh2[i]; }
        sh[0] = a; sh2[0] = a2;
    }
    __syncthreads();
    float mu = sh[0] * (1.f / Dd);
    float var = sh2[0] * (1.f / Dd) - mu * mu;
    float r = rsqrtf(var + 1e-5f);
    g_xnorm[row * Dd + tid] = (v - mu) * r * g[tid] + b[tid];
}

// ---------------- conv_w transpose: (O,I,4) -> (4,O,I) ----------------
__global__ void k_convwt(const float* __restrict__ cw) {
    int idx = blockIdx.x * 256 + threadIdx.x;
    float4 w = *(const float4*)(cw + (size_t)idx * 4);
    g_convwt[0 * 262144 + idx] = w.x;
    g_convwt[1 * 262144 + idx] = w.y;
    g_convwt[2 * 262144 + idx] = w.z;
    g_convwt[3 * 262144 + idx] = w.w;
}

// ---------------- generic TN GEMM (double-buffered, packed FMA) --------------
// blockIdx.z==1 switches to (W2, bias2, C2) -- used to fuse left/right proj.
// epi 0: C = acc + bias[n]
// epi 1: C = sigmoid(acc + bias[n])
// epi 2: groupnorm/skip epilogue (bias=gn_g, extra=gn_b) -> C
// epi 3: C = acc + bias[n] + extra[m*N+n]
__global__ __launch_bounds__(256) void k_gemm(const float* __restrict__ A,
                                              const float* __restrict__ W,
                                              const float* __restrict__ bias,
                                              const float* __restrict__ extra,
                                              float* __restrict__ C,
                                              const float* __restrict__ W2,
                                              const float* __restrict__ bias2,
                                              float* __restrict__ C2,
                                              int N, int K, int epi) {
    if (blockIdx.z == 1) { W = W2; bias = bias2; C = C2; }
    __shared__ __align__(16) float As[2][BK][BM + 4];
    __shared__ __align__(16) float Bs[2][BK][BN + 4];
    int tid = threadIdx.x;
    int m0 = blockIdx.y * BM, n0 = blockIdx.x * BN;
    int lr = tid >> 2, lk = (tid & 3) * 4;
    int ty = tid >> 4, tx = tid & 15;
    const float* Ap = A + (size_t)(m0 + lr) * K + lk;
    const float* Wp = W + (size_t)(n0 + lr) * K + lk;
    ull acc[4][2] = {};
    float4 a = *(const float4*)Ap;
    float4 w = *(const float4*)Wp;
    STS_TILE(0, a, w);
    __syncthreads();
    int buf = 0;
    for (int k0 = BK; k0 < K; k0 += BK) {
        float4 a2 = *(const float4*)(Ap + k0);
        float4 w2 = *(const float4*)(Wp + k0);
        mma_tile2(As[buf], Bs[buf], ty, tx, acc);
        STS_TILE(buf ^ 1, a2, w2);
        __syncthreads();
        buf ^= 1;
    }
    mma_tile2(As[buf], Bs[buf], ty, tx, acc);

#pragma unroll
    for (int i = 0; i < 4; i++) {
        int m = m0 + ty * 4 + i;
        int n = n0 + tx * 4;
        float2 p0 = unpackf2(acc[i][0]);
        float2 p1 = unpackf2(acc[i][1]);
        float vv[4] = {p0.x, p0.y, p1.x, p1.y};
        float4 b4 = *(const float4*)&bias[n];
        float bb[4] = {b4.x, b4.y, b4.z, b4.w};
        float4 outv;
        float* ov = &outv.x;
        if (epi == 0) {
#pragma unroll
            for (int j = 0; j < 4; j++) ov[j] = vv[j] + bb[j];
        } else if (epi == 1) {
#pragma unroll
            for (int j = 0; j < 4; j++) ov[j] = sigm(vv[j] + bb[j]);
        } else if (epi == 2) {
            int b = m >> 8, hh = n >> 7;
            float mu = g_gnmu[b * 4 + hh], rs = g_gnrs[b * 4 + hh];
            float4 hs = *(const float4*)&g_hseq[(size_t)m * D2 + n];
            float4 xr4 = *(const float4*)&g_xright[(size_t)m * D2 + n];
            float4 e4 = *(const float4*)&extra[n];
            float hsv[4] = {hs.x, hs.y, hs.z, hs.w};
            float xrv[4] = {xr4.x, xr4.y, xr4.z, xr4.w};
            float ev[4] = {e4.x, e4.y, e4.z, e4.w};
#pragma unroll
            for (int j = 0; j < 4; j++) {
                float zn = (hsv[j] - mu) * rs;
                float hg = zn * bb[j] + ev[j] + vv[j];
                ov[j] = hg * xrv[j] * sigm(xrv[j]);
            }
        } else {
            float4 e4 = *(const float4*)&extra[(size_t)m * N + n];
            float ev[4] = {e4.x, e4.y, e4.z, e4.w};
#pragma unroll
            for (int j = 0; j < 4; j++) ov[j] = vv[j] + bb[j] + ev[j];
        }
        *(float4*)&C[(size_t)m * N + n] = outv;
    }
}

// ---------------- causal conv1d (k=4, pad 3) as GEMM, swish epilogue ---------
__global__ __launch_bounds__(256) void k_conv(const float* __restrict__ cb) {
    __shared__ __align__(16) float As[2][BK][BM + 4];
    __shared__ __align__(16) float Bs[2][BK][BN + 4];
    int tid = threadIdx.x;
    int m0 = blockIdx.y * BM, n0 = blockIdx.x * BN;
    int lr = tid >> 2, lk = (tid & 3) * 4;
    int ty = tid >> 4, tx = tid & 15;
    int row = m0 + lr, b = row >> 8, t = row & 255;
    ull acc[4][2] = {};

#define CONV_LDA(K0, DST)                                                            \
    do {                                                                             \
        int tau = (K0) >> 9;                                                         \
        int ii = ((K0) & 511) + lk;                                                  \
        int tp = t - 3 + tau;                                                        \
        DST = make_float4(0.f, 0.f, 0.f, 0.f);                                       \
        if (tp >= 0) DST = *(const float4*)(g_xleft + (size_t)(b * Tt + tp) * D2 + ii); \
    } while (0)
#define CONV_LDB(K0, DST)                                                            \
    do {                                                                             \
        int tau = (K0) >> 9;                                                         \
        int ii = ((K0) & 511) + lk;                                                  \
        DST = *(const float4*)(g_convwt + (size_t)tau * 262144 + (size_t)(n0 + lr) * D2 + ii); \
    } while (0)

    float4 a, w;
    CONV_LDA(0, a);
    CONV_LDB(0, w);
    STS_TILE(0, a, w);
    __syncthreads();
    int buf = 0;
    for (int k0 = BK; k0 < 2048; k0 += BK) {
        float4 a2, w2;
        CONV_LDA(k0, a2);
        CONV_LDB(k0, w2);
        mma_tile2(As[buf], Bs[buf], ty, tx, acc);
        STS_TILE(buf ^ 1, a2, w2);
        __syncthreads();
        buf ^= 1;
    }
    mma_tile2(As[buf], Bs[buf], ty, tx, acc);

#pragma unroll
    for (int i = 0; i < 4; i++) {
        int m = m0 + ty * 4 + i;
        int n = n0 + tx * 4;
        float2 p0 = unpackf2(acc[i][0]);
        float2 p1 = unpackf2(acc[i][1]);
        float vv[4] = {p0.x, p0.y, p1.x, p1.y};
        float4 b4 = *(const float4*)&cb[n];
        float bb[4] = {b4.x, b4.y, b4.z, b4.w};
        float4 outv;
        float* ov = &outv.x;
#pragma unroll
        for (int j = 0; j < 4; j++) {
            float z = vv[j] + bb[j];
            ov[j] = z * sigm(z);
        }
        *(float4*)&g_xtrans[(size_t)m * D2 + n] = outv;
    }
}

// ---------------- block-diagonal q/k/v projections ----------------
__global__ __launch_bounds__(256) void k_qkv(const float* __restrict__ Wq,
                                             const float* __restrict__ Wk,
                                             const float* __restrict__ Wv) {
    __shared__ __align__(16) float As[2][BK][BM + 4];
    __shared__ __align__(16) float Bs[2][BK][BN + 4];
    int tid = threadIdx.x;
    int z = blockIdx.z, which = z >> 2, h = z & 3;
    const float* src = (which == 2) ? g_xleft : g_xtrans;
    const float* W = (which == 0) ? Wq : ((which == 1) ? Wk : Wv);
    float* dst = (which == 0) ? g_q : ((which == 1) ? g_k : g_v);
    float sc = (which == 1) ? SCALEF : 1.f;
    int m0 = blockIdx.y * BM, n0 = blockIdx.x * BN;
    int lr = tid >> 2, lk = (tid & 3) * 4;
    int ty = tid >> 4, tx = tid & 15;
    const float* Ap = src + (size_t)(m0 + lr) * D2 + h * 128 + lk;
    const float* Wp = W + (size_t)h * 16384 + (size_t)(n0 + lr) * 128 + lk;
    ull acc[4][2] = {};
    float4 a = *(const float4*)Ap;
    float4 w = *(const float4*)Wp;
    STS_TILE(0, a, w);
    __syncthreads();
    int buf = 0;
    for (int k0 = BK; k0 < 128; k0 += BK) {
        float4 a2 = *(const float4*)(Ap + k0);
        float4 w2 = *(const float4*)(Wp + k0);
        mma_tile2(As[buf], Bs[buf], ty, tx, acc);
        STS_TILE(buf ^ 1, a2, w2);
        __syncthreads();
        buf ^= 1;
    }
    mma_tile2(As[buf], Bs[buf], ty, tx, acc);
#pragma unroll
    for (int i = 0; i < 4; i++) {
        float2 p0 = unpackf2(acc[i][0]);
        float2 p1 = unpackf2(acc[i][1]);
        float4 outv = make_float4(sc * p0.x, sc * p0.y, sc * p1.x, sc * p1.y);
        *(float4*)&dst[(size_t)(m0 + ty * 4 + i) * D2 + h * 128 + n0 + tx * 4] = outv;
    }
}

// ---------------- i_bar / f_bar GEMV + zero rowsum ----------------
__global__ void k_ibfb(const float* __restrict__ Wi, const float* __restrict__ Wf,
                       const float* __restrict__ bi, const float* __restrict__ bf) {
    int row = blockIdx.x * 8 + (threadIdx.x >> 5);
    int l = threadIdx.x & 31;
    const float* xr = g_xleft + (size_t)row * D2;
    float si = 0, sf = 0;
#pragma unroll 4
    for (int j = l; j < D2; j += 32) {
        float v = xr[j];
        si += v * Wi[j];
        sf += v * Wf[j];
    }
#pragma unroll
    for (int o = 16; o; o >>= 1) {
        si += __shfl_xor_sync(0xffffffffu, si, o);
        sf += __shfl_xor_sync(0xffffffffu, sf, o);
    }
    if (l == 0) {
        g_ib[row] = si + bi[0];
        g_fb[row] = sf + bf[0];
        g_rowsum[row] = 0.f;
    }
}

// ---------------- scalar gate scan ----------------
__global__ void k_scan() {
    int b = threadIdx.x;
    if (b < Bq) {
        float m = 0.f, F = 0.f;
        for (int t = 0; t < Tt; t++) {
            float ib = g_ib[b * Tt + t], fb = g_fb[b * Tt + t];
            float mn = fmaxf(fb + m, ib);
            F += fb;
            g_alpha[b * Tt + t] = ib - F;
            g_beta[b * Tt + t] = F - mn;
            m = mn;
        }
    }
}

// ---------------- attention scores: A[t][s] = exp(a_s+b_t)*(q_t.k_s) --------
__global__ __launch_bounds__(256) void k_attn1() {
    int tid = threadIdx.x;
    int z = blockIdx.z;
    int m0 = blockIdx.y * BM, n0 = blockIdx.x * BN;
    int ty = tid >> 4, tx = tid & 15;
    if (n0 > m0 + (BM - 1)) {  // fully masked tile: zero-fill, no rowsum contribution
        float4 z4 = make_float4(0.f, 0.f, 0.f, 0.f);
#pragma unroll
        for (int i = 0; i < 4; i++)
            *(float4*)&g_A[(size_t)z * Tt * Tt + (size_t)(m0 + ty * 4 + i) * Tt + n0 + tx * 4] = z4;
        return;
    }
    __shared__ __align__(16) float As[2][BK][BM + 4];
    __shared__ __align__(16) float Bs[2][BK][BN + 4];
    int lr = tid >> 2, lk = (tid & 3) * 4;
    const float* Ap = g_q + (size_t)(z * Tt + m0 + lr) * D2 + lk;
    const float* Wp = g_k + (size_t)(z * Tt + n0 + lr) * D2 + lk;
    ull acc[4][2] = {};
    float4 a = *(const float4*)Ap;
    float4 w = *(const float4*)Wp;
    STS_TILE(0, a, w);
    __syncthreads();
    int buf = 0;
    for (int k0 = BK; k0 < D2; k0 += BK) {
        float4 a2 = *(const float4*)(Ap + k0);
        float4 w2 = *(const float4*)(Wp + k0);
        mma_tile2(As[buf], Bs[buf], ty, tx, acc);
        STS_TILE(buf ^ 1, a2, w2);
        __syncthreads();
        buf ^= 1;
    }
    mma_tile2(As[buf], Bs[buf], ty, tx, acc);

    float al[4], be[4];
#pragma unroll
    for (int j = 0; j < 4; j++) al[j] = g_alpha[z * Tt + n0 + tx * 4 + j];
#pragma unroll
    for (int i = 0; i < 4; i++) be[i] = g_beta[z * Tt + m0 + ty * 4 + i];
#pragma unroll
    for (int i = 0; i < 4; i++) {
        int t = m0 + ty * 4 + i;
        float2 p0 = unpackf2(acc[i][0]);
        float2 p1 = unpackf2(acc[i][1]);
        float vv[4] = {p0.x, p0.y, p1.x, p1.y};
        float4 outv;
        float* ov = &outv.x;
        float p = 0.f;
#pragma unroll
        for (int j = 0; j < 4; j++) {
            int s = n0 + tx * 4 + j;
            float v = (s <= t) ? __expf(al[j] + be[i]) * vv[j] : 0.f;
            ov[j] = v;
            p += v;
        }
        *(float4*)&g_A[(size_t)z * Tt * Tt + (size_t)t * Tt + n0 + tx * 4] = outv;
#pragma unroll
        for (int off = 1; off < 16; off <<= 1) p += __shfl_xor_sync(0xffffffffu, p, off);
        if (tx == 0) atomicAdd(&g_rowsum[z * Tt + t], p);
    }
}

// ---------------- h = (A @ V) / denom * o (NN GEMM) ----------------
__global__ __launch_bounds__(256) void k_attn2() {
    __shared__ __align__(16) float As[2][BK][BM + 4];
    __shared__ __align__(16) float Bs[2][BK][BN + 4];
    int tid = threadIdx.x;
    int z = blockIdx.z;
    int m0 = blockIdx.y * BM, n0 = blockIdx.x * BN;
    int lr = tid >> 2, lk = (tid & 3) * 4;
    int ty = tid >> 4, tx = tid & 15;
    int brow = tid >> 4, bcol = (tid & 15) * 4;
    const float* Ap = g_A + (size_t)z * Tt * Tt + (size_t)(m0 + lr) * Tt + lk;
    const float* Vb = g_v + (size_t)z * Tt * D2;
    ull acc[4][2] = {};
    float4 a = *(const float4*)Ap;
    float4 w = *(const float4*)(Vb + (size_t)brow * D2 + n0 + bcol);
    As[0][lk + 0][lr] = a.x; As[0][lk + 1][lr] = a.y;
    As[0][lk + 2][lr] = a.z; As[0][lk + 3][lr] = a.w;
    *(float4*)&Bs[0][brow][bcol] = w;
    __syncthreads();
    int buf = 0;
    for (int k0 = BK; k0 < Tt; k0 += BK) {
        float4 a2 = *(const float4*)(Ap + k0);
        float4 w2 = *(const float4*)(Vb + (size_t)(k0 + brow) * D2 + n0 + bcol);
        mma_tile2(As[buf], Bs[buf], ty, tx, acc);
        As[buf ^ 1][lk + 0][lr] = a2.x; As[buf ^ 1][lk + 1][lr] = a2.y;
        As[buf ^ 1][lk + 2][lr] = a2.z; As[buf ^ 1][lk + 3][lr] = a2.w;
        *(float4*)&Bs[buf ^ 1][brow][bcol] = w2;
        __syncthreads();
        buf ^= 1;
    }
    mma_tile2(As[buf], Bs[buf], ty, tx, acc);

#pragma unroll
    for (int i = 0; i < 4; i++) {
        int m = m0 + ty * 4 + i;
        int r = z * Tt + m;
        float rs = g_rowsum[r];
        float dn = fmaxf(fabsf(rs), 1.f) + 1e-8f;
        float inv = 1.f / dn;
        float2 p0 = unpackf2(acc[i][0]);
        float2 p1 = unpackf2(acc[i][1]);
        float4 og = *(const float4*)&g_o[(size_t)r * D2 + n0 + tx * 4];
        float4 outv = make_float4(p0.x * inv * og.x, p0.y * inv * og.y,
                                  p1.x * inv * og.z, p1.y * inv * og.w);
        *(float4*)&g_hseq[(size_t)r * D2 + n0 + tx * 4] = outv;
    }
}

// ---------------- GroupNorm stats over (T, DH) per (b, h) ----------------
__global__ void k_gnstats() {
    int bh = blockIdx.x;
    int b = bh >> 2, h = bh & 3;
    int tid = threadIdx.x;
    float s = 0, s2 = 0;
    const float* base = g_hseq + (size_t)(b * Tt) * D2 + h * 128;
    for (int i = tid; i < Tt * 128; i += 256) {
        int t = i >> 7, d = i & 127;
        float v = base[(size_t)t * D2 + d];
        s += v; s2 += v * v;
    }
#pragma unroll
    for (int o = 16; o; o >>= 1) {
        s += __shfl_xor_sync(0xffffffffu, s, o);
        s2 += __shfl_xor_sync(0xffffffffu, s2, o);
    }
    __shared__ float sh[8], sh2[8];
    int w = tid >> 5, l = tid & 31;
    if (l == 0) { sh[w] = s; sh2[w] = s2; }
    __syncthreads();
    if (tid == 0) {
        float a = 0, a2 = 0;
#pragma unroll
        for (int i = 0; i < 8; i++) { a += sh[i]; a2 += sh2[i]; }
        float mu = a * (1.f / (Tt * 128));
        float var = a2 * (1.f / (Tt * 128)) - mu * mu;
        g_gnmu[bh] = mu;
        g_gnrs[bh] = rsqrtf(var + 1e-5f);
    }
}

// ---------------- launch ----------------
extern "C" void kernel_launch(void* const* d_in, const int* in_sizes, int n_in,
                              void* d_out, int out_size) {
    const float* x       = (const float*)d_in[0];
    const float* ln_g    = (const float*)d_in[1];
    const float* ln_b    = (const float*)d_in[2];
    const float* W_left  = (const float*)d_in[3];
    const float* b_left  = (const float*)d_in[4];
    const float* W_right = (const float*)d_in[5];
    const float* b_right = (const float*)d_in[6];
    const float* Wi      = (const float*)d_in[7];
    const float* bi      = (const float*)d_in[8];
    const float* Wf      = (const float*)d_in[9];
    const float* bf      = (const float*)d_in[10];
    const float* Wo      = (const float*)d_in[11];
    const float* bo      = (const float*)d_in[12];
    const float* Wq      = (const float*)d_in[13];
    const float* Wk      = (const float*)d_in[14];
    const float* Wv      = (const float*)d_in[15];
    const float* conv_w  = (const float*)d_in[16];
    const float* conv_b  = (const float*)d_in[17];
    const float* skip_W  = (const float*)d_in[18];
    const float* gn_g    = (const float*)d_in[19];
    const float* gn_b    = (const float*)d_in[20];
    const float* W_last  = (const float*)d_in[21];
    const float* b_last  = (const float*)d_in[22];
    float* out = (float*)d_out;

    float *p_xnorm, *p_xleft, *p_xright, *p_xtrans, *p_o, *p_h;
    cudaGetSymbolAddress((void**)&p_xnorm, g_xnorm);
    cudaGetSymbolAddress((void**)&p_xleft, g_xleft);
    cudaGetSymbolAddress((void**)&p_xright, g_xright);
    cudaGetSymbolAddress((void**)&p_xtrans, g_xtrans);
    cudaGetSymbolAddress((void**)&p_o, g_o);
    cudaGetSymbolAddress((void**)&p_h, g_h);

    k_layernorm<<<BT, 256>>>(x, ln_g, ln_b);
    k_convwt<<<1024, 256>>>(conv_w);
    // fused left+right projections (grid.z picks the weight set)
    k_gemm<<<dim3(8, 16, 2), 256>>>(p_xnorm, W_left, b_left, nullptr, p_xleft,
                                    W_right, b_right, p_xright, 512, 256, 0);
    k_conv<<<dim3(8, 16), 256>>>(conv_b);
    k_gemm<<<dim3(8, 16, 1), 256>>>(p_xleft, Wo, bo, nullptr, p_o,
                                    nullptr, nullptr, nullptr, 512, 512, 1);
    k_ibfb<<<128, 256>>>(Wi, Wf, bi, bf);
    k_scan<<<1, 32>>>();
    k_qkv<<<dim3(2, 16, 12), 256>>>(Wq, Wk, Wv);
    k_attn1<<<dim3(4, 4, 4), 256>>>();
    k_attn2<<<dim3(8, 4, 4), 256>>>();
    k_gnstats<<<16, 256>>>();
    k_gemm<<<dim3(8, 16, 1), 256>>>(p_xtrans, skip_W, gn_g, gn_b, p_h,
                                    nullptr, nullptr, nullptr, 512, 512, 2);
    k_gemm<<<dim3(4, 16, 1), 256>>>(p_h, W_last, b_last, x, out,
                                    nullptr, nullptr, nullptr, 256, 512, 3);
}